// round 5
// baseline (speedup 1.0000x reference)
#include <cuda_runtime.h>
#include <cuda_bf16.h>
#include <cstdint>

#define NN 50000
#define NE 800000
#define HD 128
#define SCAN_B 256
#define NBLK ((NN + SCAN_B - 1) / SCAN_B)   // 196
#define GB   ((NN + 127) / 128)             // 391 gemm tiles

#if defined(__CUDA_ARCH__) && (__CUDA_ARCH__ >= 1000) && \
    (defined(__CUDA_ARCH_FEAT_SM103_ALL) || defined(__CUDA_ARCH_FEAT_SM100_ALL))
#define HAS_TC 1
#else
#define HAS_TC 0
#endif

// ---------------- scratch (__device__ globals: allocation-free) ----------------
__device__ int g_idx64;
__device__ int g_cnt[NN + 1];
__device__ int g_off[NN + 1];
__device__ int g_cur[NN];
__device__ int g_csr[NE];
__device__ int g_part[NBLK];
__device__ int g_partpre[NBLK];
__device__ __align__(16) float g_z[NN * HD];      // agg out / gemm2 out (reused)
__device__ __align__(16) float g_h1[NN * HD];     // gemm1 out
__device__ __align__(16) float g_h[NN * HD];      // layer-0 out
__device__ __align__(16) unsigned char g_wimg[4][65536];   // W bf16 hi/lo B-operand images
__device__ float g_sum[2][HD];
__device__ float g_sq[2][HD];
__device__ __align__(16) float g_scale[HD];
__device__ __align__(16) float g_shift[HD];

// ---------------- helpers ----------------
__device__ __forceinline__ uint32_t smem_u32(const void* p) {
    uint32_t a;
    asm("{ .reg .u64 t; cvta.to.shared.u64 t, %1; cvt.u32.u64 %0, t; }" : "=r"(a) : "l"(p));
    return a;
}

// Blocked SW128 atom layout for a 128x128 bf16 tile: atom = 8 rows x 64 cols
// (1024B); atom_offset = (r/8) + (c/64)*16. XOR swizzle at 16B granularity.
__device__ __forceinline__ uint32_t tile_off(int r, int c) {
    uint32_t b = (uint32_t)((((r >> 3) + ((c >> 6) << 4)) << 10) + ((r & 7) << 7) + ((c & 63) << 1));
    return b ^ ((b >> 3) & 0x70);
}

__device__ __forceinline__ void split_bf16(float v, unsigned short& hi, unsigned short& lo) {
    __nv_bfloat16 h = __float2bfloat16_rn(v);
    float res = v - __bfloat162float(h);
    __nv_bfloat16 l = __float2bfloat16_rn(res);
    hi = __bfloat16_as_ushort(h);
    lo = __bfloat16_as_ushort(l);
}

__device__ __forceinline__ uint32_t pack2(unsigned short a, unsigned short b) {
    return (uint32_t)a | ((uint32_t)b << 16);
}

// ---------------- edge dtype detection (int32 vs int64) ----------------
__global__ void k_detect(const unsigned int* __restrict__ w) {
    if (threadIdx.x == 0) {
        int is64 = 1;
        for (int i = 1; i < 64; i += 2)
            if (w[i] != 0u) is64 = 0;
        g_idx64 = is64;
    }
}

__device__ __forceinline__ int edge_at(const void* ei, long long i) {
    return g_idx64 ? (int)((const long long*)ei)[i] : ((const int*)ei)[i];
}

// ---------------- CSR build ----------------
__global__ void k_zero() {
    int i = blockIdx.x * blockDim.x + threadIdx.x;
    if (i <= NN) g_cnt[i] = 0;
    if (i < HD) {
        g_sum[0][i] = 0.f; g_sq[0][i] = 0.f;
        g_sum[1][i] = 0.f; g_sq[1][i] = 0.f;
    }
}

__global__ void k_hist(const void* __restrict__ ei) {
    int e = blockIdx.x * blockDim.x + threadIdx.x;
    if (e < NE) {
        int d = edge_at(ei, (long long)NE + e);
        atomicAdd(&g_cnt[d], 1);
    }
}

__global__ void k_blocksum() {
    __shared__ int red[SCAN_B];
    int t = threadIdx.x;
    int i = blockIdx.x * SCAN_B + t;
    red[t] = (i < NN) ? g_cnt[i] : 0;
    __syncthreads();
    #pragma unroll
    for (int d = SCAN_B / 2; d > 0; d >>= 1) {
        if (t < d) red[t] += red[t + d];
        __syncthreads();
    }
    if (t == 0) g_part[blockIdx.x] = red[0];
}

__global__ void k_scanpart() {
    __shared__ int s[SCAN_B];
    int t = threadIdx.x;
    int v = (t < NBLK) ? g_part[t] : 0;
    s[t] = v;
    __syncthreads();
    #pragma unroll
    for (int d = 1; d < SCAN_B; d <<= 1) {
        int u = (t >= d) ? s[t - d] : 0;
        __syncthreads();
        s[t] += u;
        __syncthreads();
    }
    if (t < NBLK) g_partpre[t] = s[t] - v;
    if (t == 0) g_off[NN] = NE;
}

__global__ void k_offsets() {
    __shared__ int s[SCAN_B];
    int t = threadIdx.x;
    int i = blockIdx.x * SCAN_B + t;
    int v = (i < NN) ? g_cnt[i] : 0;
    s[t] = v;
    __syncthreads();
    #pragma unroll
    for (int d = 1; d < SCAN_B; d <<= 1) {
        int u = (t >= d) ? s[t - d] : 0;
        __syncthreads();
        s[t] += u;
        __syncthreads();
    }
    if (i < NN) {
        int o = g_partpre[blockIdx.x] + s[t] - v;
        g_off[i] = o;
        g_cur[i] = o;
    }
}

__global__ void k_scatter(const void* __restrict__ ei) {
    int e = blockIdx.x * blockDim.x + threadIdx.x;
    if (e < NE) {
        int d = edge_at(ei, (long long)NE + e);
        int s = edge_at(ei, e);
        int p = atomicAdd(&g_cur[d], 1);
        g_csr[p] = s;
    }
}

// ---------------- aggregation: z[i] = h[i] + sum_{j in N(i)} h[j] ----------------
__global__ void __launch_bounds__(256) k_agg(const float* __restrict__ h,
                                             float* __restrict__ z) {
    int node = blockIdx.x * 8 + (threadIdx.x >> 5);
    if (node >= NN) return;
    int lane = threadIdx.x & 31;
    const float4* hv = (const float4*)h;
    float4 acc = hv[(size_t)node * 32 + lane];
    int b = g_off[node], e = g_off[node + 1];
    for (int j = b; j < e; j++) {
        int s = g_csr[j];
        float4 v = __ldg(&hv[(size_t)s * 32 + lane]);
        acc.x += v.x; acc.y += v.y; acc.z += v.z; acc.w += v.w;
    }
    ((float4*)z)[(size_t)node * 32 + lane] = acc;
}

// ---------------- W -> B-operand images (row=n, col=k, hi/lo, swizzled) ----------------
__global__ void k_wprep(const float* __restrict__ w, unsigned char* __restrict__ img) {
    int i = blockIdx.x * blockDim.x + threadIdx.x;
    if (i < HD * HD) {
        int k = i >> 7, n = i & 127;          // w[k][n]
        unsigned short hi, lo;
        split_bf16(w[i], hi, lo);
        uint32_t off = tile_off(n, k);
        *(unsigned short*)(img + off)         = hi;
        *(unsigned short*)(img + 32768 + off) = lo;
    }
}

// ---------------- GEMM: C = act(A @ W + bias) ----------------
constexpr size_t SMEM_BYTES = 133120;

#if HAS_TC
// tcgen05 path smem layout
constexpr int TG_SM_A    = 1024;                    // A bf16 hi(32K)+lo(32K)
constexpr int TG_SM_W    = TG_SM_A + 65536;         // W bf16 hi+lo
constexpr int TG_SM_BIAS = TG_SM_W + 65536;

#define TC_ALLOC(sm, n)   asm volatile("tcgen05.alloc.cta_group::1.sync.aligned.shared::cta.b32 [%0], %1;" :: "r"(sm), "r"(n) : "memory")
#define TC_DEALLOC(t, n)  asm volatile("tcgen05.dealloc.cta_group::1.sync.aligned.b32 %0, %1;" :: "r"(t), "r"(n))
#define TC_RELINQ()       asm volatile("tcgen05.relinquish_alloc_permit.cta_group::1.sync.aligned;")
#define TC_COMMIT(mb)     asm volatile("tcgen05.commit.cta_group::1.mbarrier::arrive::one.shared::cluster.b64 [%0];" :: "r"(mb) : "memory")
#define TC_FENCE_AFTER()  asm volatile("tcgen05.fence::after_thread_sync;" ::: "memory")
#define TC_FENCE_BEFORE() asm volatile("tcgen05.fence::before_thread_sync;" ::: "memory")
#define TC_WAIT_LD()      asm volatile("tcgen05.wait::ld.sync.aligned;" ::: "memory")
#define MBAR_INIT(a, c)   asm volatile("mbarrier.init.shared.b64 [%0], %1;" :: "r"(a), "r"(c) : "memory")
#define MBAR_WAIT0(a) do {                                                         \
    asm volatile("{\n\t.reg .pred P1;\n\t"                                         \
        "WL_%=:\n\t"                                                               \
        "mbarrier.try_wait.parity.acquire.cta.shared::cta.b64 P1, [%0], 0, 0x989680;\n\t" \
        "@P1 bra.uni WD_%=;\n\t"                                                   \
        "bra.uni WL_%=;\n\t"                                                       \
        "WD_%=:\n\t}" :: "r"(a) : "memory");                                       \
} while (0)
#define TC_LD_X32(r, ta) \
    asm volatile("tcgen05.ld.sync.aligned.32x32b.x32.b32 " \
        "{%0, %1, %2, %3, %4, %5, %6, %7, %8, %9, %10, %11, %12, %13, %14, %15, " \
        " %16, %17, %18, %19, %20, %21, %22, %23, %24, %25, %26, %27, %28, %29, %30, %31}, [%32];" \
        : "=r"((r)[0]),  "=r"((r)[1]),  "=r"((r)[2]),  "=r"((r)[3]), \
          "=r"((r)[4]),  "=r"((r)[5]),  "=r"((r)[6]),  "=r"((r)[7]), \
          "=r"((r)[8]),  "=r"((r)[9]),  "=r"((r)[10]), "=r"((r)[11]), \
          "=r"((r)[12]), "=r"((r)[13]), "=r"((r)[14]), "=r"((r)[15]), \
          "=r"((r)[16]), "=r"((r)[17]), "=r"((r)[18]), "=r"((r)[19]), \
          "=r"((r)[20]), "=r"((r)[21]), "=r"((r)[22]), "=r"((r)[23]), \
          "=r"((r)[24]), "=r"((r)[25]), "=r"((r)[26]), "=r"((r)[27]), \
          "=r"((r)[28]), "=r"((r)[29]), "=r"((r)[30]), "=r"((r)[31]) \
        : "r"(ta))

static constexpr uint64_t DESC_BASE =
    (uint64_t(2) << 61) | (uint64_t(1) << 46) | (uint64_t(64) << 32) | (uint64_t(1) << 16);
__device__ __forceinline__ uint64_t mk_desc(uint32_t addr) {
    return DESC_BASE | ((uint64_t)(addr >> 4) & 0x3FFF);
}
// idesc kind::f16: dtype F32, a/b BF16 K-major, M=128, N=128
#define IDESC_F16 ((8u << 24) | (16u << 17) | (1u << 10) | (1u << 7) | (1u << 4))

__device__ __forceinline__ void mma_f16_ss(uint32_t d, uint64_t ad, uint64_t bd, uint32_t en) {
    asm volatile(
        "{\n\t.reg .pred p;\n\tsetp.ne.u32 p, %5, 0;\n\t"
        "tcgen05.mma.cta_group::1.kind::f16 [%0], %1, %2, %3, {%4, %4, %4, %4}, p;\n\t}"
        :: "r"(d), "l"(ad), "l"(bd), "r"(IDESC_F16), "r"(0u), "r"(en) : "memory");
}
#else
// FFMA2 fallback smem layout
constexpr int AS    = 129;
constexpr int W_ELE = HD * HD;      // 16384 floats
#endif

template <bool RELU>
__global__ void __launch_bounds__(256, 1) k_gemm(const float* __restrict__ A,
                                                 const float* __restrict__ W,
                                                 const unsigned char* __restrict__ Wimg,
                                                 const float* __restrict__ bias,
                                                 float* __restrict__ C) {
    extern __shared__ unsigned char smc[];
    int tid = threadIdx.x;
    int m0 = blockIdx.x * 128;

#if HAS_TC
    uint32_t sb = smem_u32(smc);
    int wid = tid >> 5, lid = tid & 31;

    if (wid == 0) TC_ALLOC(sb, 128);

    // A: fp32 rows -> bf16 hi/lo swizzled tile. Thread i handles half-row.
    {
        int row = tid >> 1, half = tid & 1;
        int grow = m0 + row;
        const float4* ar = (grow < NN) ? (const float4*)(A + (size_t)grow * HD + half * 64) : nullptr;
        #pragma unroll
        for (int j = 0; j < 8; j++) {                 // 8 cols per chunk
            float4 v0 = ar ? ar[2 * j]     : make_float4(0.f, 0.f, 0.f, 0.f);
            float4 v1 = ar ? ar[2 * j + 1] : make_float4(0.f, 0.f, 0.f, 0.f);
            unsigned short h[8], l[8];
            split_bf16(v0.x, h[0], l[0]); split_bf16(v0.y, h[1], l[1]);
            split_bf16(v0.z, h[2], l[2]); split_bf16(v0.w, h[3], l[3]);
            split_bf16(v1.x, h[4], l[4]); split_bf16(v1.y, h[5], l[5]);
            split_bf16(v1.z, h[6], l[6]); split_bf16(v1.w, h[7], l[7]);
            uint32_t off = tile_off(row, half * 64 + j * 8);
            *(uint4*)(smc + TG_SM_A + off) =
                make_uint4(pack2(h[0], h[1]), pack2(h[2], h[3]), pack2(h[4], h[5]), pack2(h[6], h[7]));
            *(uint4*)(smc + TG_SM_A + 32768 + off) =
                make_uint4(pack2(l[0], l[1]), pack2(l[2], l[3]), pack2(l[4], l[5]), pack2(l[6], l[7]));
        }
    }
    // W image: linear 64KB copy
    {
        const float4* ws = (const float4*)Wimg;
        float4* wd = (float4*)(smc + TG_SM_W);
        #pragma unroll
        for (int i = tid; i < 4096; i += 256) wd[i] = ws[i];
    }
    if (tid < 32) ((float4*)(smc + TG_SM_BIAS))[tid] = ((const float4*)bias)[tid];
    if (tid == 0) MBAR_INIT(sb + 16, 1);
    asm volatile("fence.proxy.async.shared::cta;" ::: "memory");
    __syncthreads();

    uint32_t tmem;
    asm volatile("ld.shared.b32 %0, [%1];" : "=r"(tmem) : "r"(sb));

    if (tid == 0) {
        uint64_t ah = mk_desc(sb + TG_SM_A);
        uint64_t al = mk_desc(sb + TG_SM_A + 32768);
        uint64_t wh = mk_desc(sb + TG_SM_W);
        uint64_t wl = mk_desc(sb + TG_SM_W + 32768);
        uint32_t en = 0;
        #pragma unroll
        for (int t = 0; t < 3; t++) {
            uint64_t a = (t == 2) ? al : ah;
            uint64_t b = (t == 1) ? wl : wh;
            #pragma unroll
            for (int s = 0; s < 8; s++) {
                // k-step s: +2 units per 16 cols; cols>=64 live at atom_col 1 (+1024 units)
                uint64_t off = (s < 4) ? (uint64_t)(s * 2) : (uint64_t)(1024 + (s - 4) * 2);
                mma_f16_ss(tmem, a + off, b + off, en);
                en = 1;
            }
        }
        TC_COMMIT(sb + 16);
    }

    MBAR_WAIT0(sb + 16);
    TC_FENCE_AFTER();

    // warps 0-3: cols 0-63; warps 4-7: cols 64-127 (same 128-row subpartitions)
    int r = (wid & 3) * 32 + lid;
    int cb = (wid >> 2) * 64;
    uint32_t d[64];
    TC_LD_X32(d,      tmem + cb);
    TC_LD_X32(d + 32, tmem + cb + 32);
    TC_WAIT_LD();
    TC_FENCE_BEFORE();

    int grow = m0 + r;
    if (grow < NN) {
        const float* bsm = (const float*)(smc + TG_SM_BIAS) + cb;
        float4* o = (float4*)(C + (size_t)grow * HD + cb);
        #pragma unroll
        for (int c = 0; c < 64; c += 4) {
            float v0 = __uint_as_float(d[c])     + bsm[c];
            float v1 = __uint_as_float(d[c + 1]) + bsm[c + 1];
            float v2 = __uint_as_float(d[c + 2]) + bsm[c + 2];
            float v3 = __uint_as_float(d[c + 3]) + bsm[c + 3];
            if (RELU) {
                v0 = fmaxf(v0, 0.f); v1 = fmaxf(v1, 0.f);
                v2 = fmaxf(v2, 0.f); v3 = fmaxf(v3, 0.f);
            }
            o[c >> 2] = make_float4(v0, v1, v2, v3);
        }
    }

    __syncthreads();
    if (wid == 0) {
        TC_RELINQ();
        TC_DEALLOC(tmem, 128);
    }
#else
    // ---------- FFMA2 fallback (proven R3 path) ----------
    float* sm  = (float*)smc;
    float* w_s = sm;                 // w_s[k][n]
    float* a_s = sm + W_ELE;         // a_s[k][row]

    const float4* W4 = (const float4*)W;
    float4* ws4 = (float4*)w_s;
    #pragma unroll
    for (int i = tid; i < W_ELE / 4; i += 256) ws4[i] = W4[i];

    #pragma unroll
    for (int i = tid; i < 128 * 32; i += 256) {
        int row = i >> 5, kq = i & 31;
        float4 v = make_float4(0.f, 0.f, 0.f, 0.f);
        int gr = m0 + row;
        if (gr < NN) v = ((const float4*)(A + (size_t)gr * HD))[kq];
        a_s[(4 * kq + 0) * AS + row] = v.x;
        a_s[(4 * kq + 1) * AS + row] = v.y;
        a_s[(4 * kq + 2) * AS + row] = v.z;
        a_s[(4 * kq + 3) * AS + row] = v.w;
    }
    __syncthreads();

    int cg = tid & 15, rg = tid >> 4;
    int c0 = cg * 8, r0 = rg * 8;

    unsigned long long acc[8][4];
    #pragma unroll
    for (int i = 0; i < 8; i++)
        #pragma unroll
        for (int j = 0; j < 4; j++) acc[i][j] = 0ull;

    #pragma unroll 4
    for (int k = 0; k < 128; k++) {
        const float* ar = a_s + k * AS + r0;
        const unsigned long long* wr = (const unsigned long long*)(w_s + k * HD + c0);
        unsigned long long wv[4];
        #pragma unroll
        for (int j = 0; j < 4; j++) wv[j] = wr[j];
        #pragma unroll
        for (int i = 0; i < 8; i++) {
            float av = ar[i];
            unsigned long long ad;
            asm("mov.b64 %0, {%1, %1};" : "=l"(ad) : "f"(av));
            #pragma unroll
            for (int j = 0; j < 4; j++)
                asm("fma.rn.f32x2 %0, %1, %2, %0;"
                    : "+l"(acc[i][j]) : "l"(ad), "l"(wv[j]));
        }
    }

    float b8[8];
    {
        float4 bb0 = ((const float4*)(bias + c0))[0];
        float4 bb1 = ((const float4*)(bias + c0))[1];
        b8[0] = bb0.x; b8[1] = bb0.y; b8[2] = bb0.z; b8[3] = bb0.w;
        b8[4] = bb1.x; b8[5] = bb1.y; b8[6] = bb1.z; b8[7] = bb1.w;
    }
    #pragma unroll
    for (int i = 0; i < 8; i++) {
        int gr = m0 + r0 + i;
        if (gr < NN) {
            float v[8];
            #pragma unroll
            for (int j = 0; j < 4; j++) {
                v[2 * j]     = __uint_as_float((unsigned)(acc[i][j] & 0xffffffffull)) + b8[2 * j];
                v[2 * j + 1] = __uint_as_float((unsigned)(acc[i][j] >> 32)) + b8[2 * j + 1];
            }
            if (RELU) {
                #pragma unroll
                for (int j = 0; j < 8; j++) v[j] = fmaxf(v[j], 0.f);
            }
            float4* cp = (float4*)(C + (size_t)gr * HD + c0);
            cp[0] = make_float4(v[0], v[1], v[2], v[3]);
            cp[1] = make_float4(v[4], v[5], v[6], v[7]);
        }
    }
#endif
}

// ---------------- BN ----------------
__global__ void __launch_bounds__(128) k_colstats(const float* __restrict__ z, int slot) {
    int c = threadIdx.x;
    float s = 0.f, q = 0.f;
    for (int r = blockIdx.x; r < NN; r += gridDim.x) {
        float v = z[(size_t)r * HD + c];
        s += v; q += v * v;
    }
    atomicAdd(&g_sum[slot][c], s);
    atomicAdd(&g_sq[slot][c], q);
}

__global__ void k_bnprep(const float* __restrict__ g,
                         const float* __restrict__ be, int slot) {
    int c = threadIdx.x;
    if (c < HD) {
        float mu  = g_sum[slot][c] * (1.0f / NN);
        float var = g_sq[slot][c] * (1.0f / NN) - mu * mu;
        float sc  = g[c] * rsqrtf(var + 1e-5f);
        g_scale[c] = sc;
        g_shift[c] = be[c] - mu * sc;
    }
}

__global__ void __launch_bounds__(256) k_bnapply(const float* __restrict__ z,
                                                 float* __restrict__ o) {
    int i = blockIdx.x * blockDim.x + threadIdx.x;
    if (i < NN * 32) {
        float4 v = ((const float4*)z)[i];
        int q = i & 31;
        float4 sc = ((const float4*)g_scale)[q];
        float4 sh = ((const float4*)g_shift)[q];
        v.x = fmaxf(fmaf(v.x, sc.x, sh.x), 0.f);
        v.y = fmaxf(fmaf(v.y, sc.y, sh.y), 0.f);
        v.z = fmaxf(fmaf(v.z, sc.z, sh.z), 0.f);
        v.w = fmaxf(fmaf(v.w, sc.w, sh.w), 0.f);
        ((float4*)o)[i] = v;
    }
}

// ---------------- launcher ----------------
extern "C" void kernel_launch(void* const* d_in, const int* in_sizes, int n_in,
                              void* d_out, int out_size) {
    (void)in_sizes; (void)n_in; (void)out_size;
    const float* x    = (const float*)d_in[0];
    const void*  ei   = d_in[1];
    const float* w1_0 = (const float*)d_in[2];
    const float* b1_0 = (const float*)d_in[3];
    const float* w2_0 = (const float*)d_in[4];
    const float* b2_0 = (const float*)d_in[5];
    const float* g_0  = (const float*)d_in[6];
    const float* be_0 = (const float*)d_in[7];
    const float* w1_1 = (const float*)d_in[8];
    const float* b1_1 = (const float*)d_in[9];
    const float* w2_1 = (const float*)d_in[10];
    const float* b2_1 = (const float*)d_in[11];
    const float* g_1  = (const float*)d_in[12];
    const float* be_1 = (const float*)d_in[13];
    float* out = (float*)d_out;

    float *zp, *h1p, *hp;
    unsigned char* wi;
    cudaGetSymbolAddress((void**)&zp,  g_z);
    cudaGetSymbolAddress((void**)&h1p, g_h1);
    cudaGetSymbolAddress((void**)&hp,  g_h);
    cudaGetSymbolAddress((void**)&wi,  g_wimg);

    cudaFuncSetAttribute(k_gemm<true>,  cudaFuncAttributeMaxDynamicSharedMemorySize, (int)SMEM_BYTES);
    cudaFuncSetAttribute(k_gemm<false>, cudaFuncAttributeMaxDynamicSharedMemorySize, (int)SMEM_BYTES);

    // CSR build
    k_detect<<<1, 32>>>((const unsigned int*)ei);
    k_zero<<<(NN + 1 + 255) / 256, 256>>>();
    k_hist<<<(NE + 255) / 256, 256>>>(ei);
    k_blocksum<<<NBLK, SCAN_B>>>();
    k_scanpart<<<1, SCAN_B>>>();
    k_offsets<<<NBLK, SCAN_B>>>();
    k_scatter<<<(NE + 255) / 256, 256>>>(ei);

    // Weight images (used by tcgen05 path; harmless otherwise)
    k_wprep<<<64, 256>>>(w1_0, wi + 0 * 65536);
    k_wprep<<<64, 256>>>(w2_0, wi + 1 * 65536);
    k_wprep<<<64, 256>>>(w1_1, wi + 2 * 65536);
    k_wprep<<<64, 256>>>(w2_1, wi + 3 * 65536);

    // Layer 0
    k_agg<<<(NN + 7) / 8, 256>>>(x, zp);
    k_gemm<true ><<<GB, 256, SMEM_BYTES>>>(zp,  w1_0, wi + 0 * 65536, b1_0, h1p);
    k_gemm<false><<<GB, 256, SMEM_BYTES>>>(h1p, w2_0, wi + 1 * 65536, b2_0, zp);
    k_colstats<<<256, 128>>>(zp, 0);
    k_bnprep<<<1, 128>>>(g_0, be_0, 0);
    k_bnapply<<<(NN * 32 + 255) / 256, 256>>>(zp, hp);

    // Layer 1
    k_agg<<<(NN + 7) / 8, 256>>>(hp, zp);
    k_gemm<true ><<<GB, 256, SMEM_BYTES>>>(zp,  w1_1, wi + 2 * 65536, b1_1, h1p);
    k_gemm<false><<<GB, 256, SMEM_BYTES>>>(h1p, w2_1, wi + 3 * 65536, b2_1, zp);
    k_colstats<<<256, 128>>>(zp, 1);
    k_bnprep<<<1, 128>>>(g_1, be_1, 1);
    k_bnapply<<<(NN * 32 + 255) / 256, 256>>>(zp, out);
}

// round 10
// speedup vs baseline: 1.1649x; 1.1649x over previous
#include <cuda_runtime.h>
#include <cuda_bf16.h>
#include <cstdint>

#define NN 50000
#define NE 800000
#define HD 128
#define SCAN_B 256
#define NBLK ((NN + SCAN_B - 1) / SCAN_B)   // 196
#define GB   ((NN + 127) / 128)             // 391 gemm tiles

#if defined(__CUDA_ARCH__) && (__CUDA_ARCH__ >= 1000) && \
    (defined(__CUDA_ARCH_FEAT_SM103_ALL) || defined(__CUDA_ARCH_FEAT_SM100_ALL))
#define HAS_TC 1
#else
#define HAS_TC 0
#endif

// ---------------- scratch (__device__ globals: allocation-free) ----------------
__device__ int g_idx64;
__device__ int g_cnt[NN + 1];
__device__ int g_off[NN + 1];
__device__ int g_cur[NN];
__device__ int g_csr[NE];
__device__ int g_part[NBLK];
__device__ int g_partpre[NBLK];
__device__ __align__(16) float g_z[NN * HD];                       // fgemm out (pre-BN)
__device__ __align__(16) unsigned char g_abuf[(size_t)GB * 65536]; // A bf16 hi/lo images
__device__ __align__(16) unsigned char g_wimg[4][65536];           // W bf16 hi/lo images
__device__ float g_sum[2][HD];
__device__ float g_sq[2][HD];
__device__ __align__(16) float g_scale[HD];
__device__ __align__(16) float g_shift[HD];

// ---------------- helpers ----------------
__device__ __forceinline__ uint32_t smem_u32(const void* p) {
    uint32_t a;
    asm("{ .reg .u64 t; cvta.to.shared.u64 t, %1; cvt.u32.u64 %0, t; }" : "=r"(a) : "l"(p));
    return a;
}

// Blocked SW128 atom layout for a 128x128 bf16 tile: atom = 8 rows x 64 cols
// (1024B); atom_offset = (r/8) + (c/64)*16. XOR swizzle at 16B granularity.
__device__ __forceinline__ uint32_t tile_off(int r, int c) {
    uint32_t b = (uint32_t)((((r >> 3) + ((c >> 6) << 4)) << 10) + ((r & 7) << 7) + ((c & 63) << 1));
    return b ^ ((b >> 3) & 0x70);
}

__device__ __forceinline__ void split_bf16(float v, unsigned short& hi, unsigned short& lo) {
    __nv_bfloat16 h = __float2bfloat16_rn(v);
    float res = v - __bfloat162float(h);
    __nv_bfloat16 l = __float2bfloat16_rn(res);
    hi = __bfloat16_as_ushort(h);
    lo = __bfloat16_as_ushort(l);
}

__device__ __forceinline__ uint32_t pack2(unsigned short a, unsigned short b) {
    return (uint32_t)a | ((uint32_t)b << 16);
}

// ---------------- edge dtype detection (int32 vs int64) ----------------
__global__ void k_detect(const unsigned int* __restrict__ w) {
    if (threadIdx.x == 0) {
        int is64 = 1;
        for (int i = 1; i < 64; i += 2)
            if (w[i] != 0u) is64 = 0;
        g_idx64 = is64;
    }
}

__device__ __forceinline__ int edge_at(const void* ei, long long i) {
    return g_idx64 ? (int)((const long long*)ei)[i] : ((const int*)ei)[i];
}

// ---------------- CSR build ----------------
__global__ void k_zero() {
    int i = blockIdx.x * blockDim.x + threadIdx.x;
    if (i <= NN) g_cnt[i] = 0;
    if (i < HD) {
        g_sum[0][i] = 0.f; g_sq[0][i] = 0.f;
        g_sum[1][i] = 0.f; g_sq[1][i] = 0.f;
    }
}

__global__ void k_hist(const void* __restrict__ ei) {
    int e = blockIdx.x * blockDim.x + threadIdx.x;
    if (e < NE) {
        int d = edge_at(ei, (long long)NE + e);
        atomicAdd(&g_cnt[d], 1);
    }
}

__global__ void k_blocksum() {
    __shared__ int red[SCAN_B];
    int t = threadIdx.x;
    int i = blockIdx.x * SCAN_B + t;
    red[t] = (i < NN) ? g_cnt[i] : 0;
    __syncthreads();
    #pragma unroll
    for (int d = SCAN_B / 2; d > 0; d >>= 1) {
        if (t < d) red[t] += red[t + d];
        __syncthreads();
    }
    if (t == 0) g_part[blockIdx.x] = red[0];
}

__global__ void k_scanpart() {
    __shared__ int s[SCAN_B];
    int t = threadIdx.x;
    int v = (t < NBLK) ? g_part[t] : 0;
    s[t] = v;
    __syncthreads();
    #pragma unroll
    for (int d = 1; d < SCAN_B; d <<= 1) {
        int u = (t >= d) ? s[t - d] : 0;
        __syncthreads();
        s[t] += u;
        __syncthreads();
    }
    if (t < NBLK) g_partpre[t] = s[t] - v;
    if (t == 0) g_off[NN] = NE;
}

__global__ void k_offsets() {
    __shared__ int s[SCAN_B];
    int t = threadIdx.x;
    int i = blockIdx.x * SCAN_B + t;
    int v = (i < NN) ? g_cnt[i] : 0;
    s[t] = v;
    __syncthreads();
    #pragma unroll
    for (int d = 1; d < SCAN_B; d <<= 1) {
        int u = (t >= d) ? s[t - d] : 0;
        __syncthreads();
        s[t] += u;
        __syncthreads();
    }
    if (i < NN) {
        int o = g_partpre[blockIdx.x] + s[t] - v;
        g_off[i] = o;
        g_cur[i] = o;
    }
}

__global__ void k_scatter(const void* __restrict__ ei) {
    int e = blockIdx.x * blockDim.x + threadIdx.x;
    if (e < NE) {
        int d = edge_at(ei, (long long)NE + e);
        int s = edge_at(ei, e);
        int p = atomicAdd(&g_cur[d], 1);
        g_csr[p] = s;
    }
}

// ---------------- aggregation (+optional fused BN+relu) -> bf16 hi/lo image ----------------
// One warp per node; lane l owns cols 4l..4l+3. Gather loop unrolled x4 for MLP.
template <bool BN>
__global__ void __launch_bounds__(256) k_aggimg(const float* __restrict__ h,
                                                unsigned char* __restrict__ img) {
    int node = blockIdx.x * 8 + (threadIdx.x >> 5);
    if (node >= NN) return;
    int lane = threadIdx.x & 31;

    float4 sc, sh;
    if (BN) {
        sc = ((const float4*)g_scale)[lane];
        sh = ((const float4*)g_shift)[lane];
    }
    const float4* hv = (const float4*)h;

    float4 acc = hv[(size_t)node * 32 + lane];
    if (BN) {
        acc.x = fmaxf(fmaf(acc.x, sc.x, sh.x), 0.f);
        acc.y = fmaxf(fmaf(acc.y, sc.y, sh.y), 0.f);
        acc.z = fmaxf(fmaf(acc.z, sc.z, sh.z), 0.f);
        acc.w = fmaxf(fmaf(acc.w, sc.w, sh.w), 0.f);
    }

    int b = g_off[node], e = g_off[node + 1];
    int j = b;
    for (; j + 4 <= e; j += 4) {
        int s0 = g_csr[j], s1 = g_csr[j + 1], s2 = g_csr[j + 2], s3 = g_csr[j + 3];
        float4 v0 = __ldg(&hv[(size_t)s0 * 32 + lane]);
        float4 v1 = __ldg(&hv[(size_t)s1 * 32 + lane]);
        float4 v2 = __ldg(&hv[(size_t)s2 * 32 + lane]);
        float4 v3 = __ldg(&hv[(size_t)s3 * 32 + lane]);
        if (BN) {
            v0.x = fmaxf(fmaf(v0.x, sc.x, sh.x), 0.f); v0.y = fmaxf(fmaf(v0.y, sc.y, sh.y), 0.f);
            v0.z = fmaxf(fmaf(v0.z, sc.z, sh.z), 0.f); v0.w = fmaxf(fmaf(v0.w, sc.w, sh.w), 0.f);
            v1.x = fmaxf(fmaf(v1.x, sc.x, sh.x), 0.f); v1.y = fmaxf(fmaf(v1.y, sc.y, sh.y), 0.f);
            v1.z = fmaxf(fmaf(v1.z, sc.z, sh.z), 0.f); v1.w = fmaxf(fmaf(v1.w, sc.w, sh.w), 0.f);
            v2.x = fmaxf(fmaf(v2.x, sc.x, sh.x), 0.f); v2.y = fmaxf(fmaf(v2.y, sc.y, sh.y), 0.f);
            v2.z = fmaxf(fmaf(v2.z, sc.z, sh.z), 0.f); v2.w = fmaxf(fmaf(v2.w, sc.w, sh.w), 0.f);
            v3.x = fmaxf(fmaf(v3.x, sc.x, sh.x), 0.f); v3.y = fmaxf(fmaf(v3.y, sc.y, sh.y), 0.f);
            v3.z = fmaxf(fmaf(v3.z, sc.z, sh.z), 0.f); v3.w = fmaxf(fmaf(v3.w, sc.w, sh.w), 0.f);
        }
        acc.x += v0.x + v1.x + v2.x + v3.x;
        acc.y += v0.y + v1.y + v2.y + v3.y;
        acc.z += v0.z + v1.z + v2.z + v3.z;
        acc.w += v0.w + v1.w + v2.w + v3.w;
    }
    for (; j < e; j++) {
        int s = g_csr[j];
        float4 v = __ldg(&hv[(size_t)s * 32 + lane]);
        if (BN) {
            v.x = fmaxf(fmaf(v.x, sc.x, sh.x), 0.f); v.y = fmaxf(fmaf(v.y, sc.y, sh.y), 0.f);
            v.z = fmaxf(fmaf(v.z, sc.z, sh.z), 0.f); v.w = fmaxf(fmaf(v.w, sc.w, sh.w), 0.f);
        }
        acc.x += v.x; acc.y += v.y; acc.z += v.z; acc.w += v.w;
    }

    unsigned short h0, h1, h2, h3, l0, l1, l2, l3;
    split_bf16(acc.x, h0, l0); split_bf16(acc.y, h1, l1);
    split_bf16(acc.z, h2, l2); split_bf16(acc.w, h3, l3);
    int tile = node >> 7, r = node & 127;
    uint32_t off = tile_off(r, lane * 4);
    unsigned char* base = img + (size_t)tile * 65536;
    *(uint2*)(base + off)         = make_uint2(pack2(h0, h1), pack2(h2, h3));
    *(uint2*)(base + 32768 + off) = make_uint2(pack2(l0, l1), pack2(l2, l3));
}

// ---------------- W -> B-operand images (row=n, col=k, hi/lo, swizzled) ----------------
__global__ void k_wprep(const float* __restrict__ w, unsigned char* __restrict__ img) {
    int i = blockIdx.x * blockDim.x + threadIdx.x;
    if (i < HD * HD) {
        int k = i >> 7, n = i & 127;          // w[k][n]
        unsigned short hi, lo;
        split_bf16(w[i], hi, lo);
        uint32_t off = tile_off(n, k);
        *(unsigned short*)(img + off)         = hi;
        *(unsigned short*)(img + 32768 + off) = lo;
    }
}

// ---------------- fused MLP: z = (relu(A@W1+b1))@W2 + b2 ----------------
constexpr int SM_A  = 1024;
constexpr int SM_W1 = SM_A + 65536;       // 66560
constexpr int SM_W2 = SM_W1 + 65536;      // 132096
constexpr int SM_B1 = SM_W2 + 65536;      // 197632
constexpr int SM_B2 = SM_B1 + 512;        // 198144
constexpr size_t FG_SMEM = SM_B2 + 512;   // 198656 (< 227KB cap)

#if HAS_TC
#define TC_ALLOC(sm, n)   asm volatile("tcgen05.alloc.cta_group::1.sync.aligned.shared::cta.b32 [%0], %1;" :: "r"(sm), "r"(n) : "memory")
#define TC_DEALLOC(t, n)  asm volatile("tcgen05.dealloc.cta_group::1.sync.aligned.b32 %0, %1;" :: "r"(t), "r"(n))
#define TC_RELINQ()       asm volatile("tcgen05.relinquish_alloc_permit.cta_group::1.sync.aligned;")
#define TC_COMMIT(mb)     asm volatile("tcgen05.commit.cta_group::1.mbarrier::arrive::one.shared::cluster.b64 [%0];" :: "r"(mb) : "memory")
#define TC_FENCE_AFTER()  asm volatile("tcgen05.fence::after_thread_sync;" ::: "memory")
#define TC_WAIT_LD()      asm volatile("tcgen05.wait::ld.sync.aligned;" ::: "memory")
#define MBAR_INIT(a, c)   asm volatile("mbarrier.init.shared.b64 [%0], %1;" :: "r"(a), "r"(c) : "memory")
#define MBAR_WAIT0(a) do {                                                         \
    asm volatile("{\n\t.reg .pred P1;\n\t"                                         \
        "WL_%=:\n\t"                                                               \
        "mbarrier.try_wait.parity.acquire.cta.shared::cta.b64 P1, [%0], 0, 0x989680;\n\t" \
        "@P1 bra.uni WD_%=;\n\t"                                                   \
        "bra.uni WL_%=;\n\t"                                                       \
        "WD_%=:\n\t}" :: "r"(a) : "memory");                                       \
} while (0)
#define TC_LD_X32(r, ta) \
    asm volatile("tcgen05.ld.sync.aligned.32x32b.x32.b32 " \
        "{%0, %1, %2, %3, %4, %5, %6, %7, %8, %9, %10, %11, %12, %13, %14, %15, " \
        " %16, %17, %18, %19, %20, %21, %22, %23, %24, %25, %26, %27, %28, %29, %30, %31}, [%32];" \
        : "=r"((r)[0]),  "=r"((r)[1]),  "=r"((r)[2]),  "=r"((r)[3]), \
          "=r"((r)[4]),  "=r"((r)[5]),  "=r"((r)[6]),  "=r"((r)[7]), \
          "=r"((r)[8]),  "=r"((r)[9]),  "=r"((r)[10]), "=r"((r)[11]), \
          "=r"((r)[12]), "=r"((r)[13]), "=r"((r)[14]), "=r"((r)[15]), \
          "=r"((r)[16]), "=r"((r)[17]), "=r"((r)[18]), "=r"((r)[19]), \
          "=r"((r)[20]), "=r"((r)[21]), "=r"((r)[22]), "=r"((r)[23]), \
          "=r"((r)[24]), "=r"((r)[25]), "=r"((r)[26]), "=r"((r)[27]), \
          "=r"((r)[28]), "=r"((r)[29]), "=r"((r)[30]), "=r"((r)[31]) \
        : "r"(ta))

static constexpr uint64_t DESC_BASE =
    (uint64_t(2) << 61) | (uint64_t(1) << 46) | (uint64_t(64) << 32) | (uint64_t(1) << 16);
__device__ __forceinline__ uint64_t mk_desc(uint32_t addr) {
    return DESC_BASE | ((uint64_t)(addr >> 4) & 0x3FFF);
}
// idesc kind::f16: dtype F32, a/b BF16 K-major, M=128, N=128
#define IDESC_F16 ((8u << 24) | (16u << 17) | (1u << 10) | (1u << 7) | (1u << 4))

__device__ __forceinline__ void mma_f16_ss(uint32_t d, uint64_t ad, uint64_t bd, uint32_t en) {
    asm volatile(
        "{\n\t.reg .pred p;\n\tsetp.ne.u32 p, %5, 0;\n\t"
        "tcgen05.mma.cta_group::1.kind::f16 [%0], %1, %2, %3, {%4, %4, %4, %4}, p;\n\t}"
        :: "r"(d), "l"(ad), "l"(bd), "r"(IDESC_F16), "r"(0u), "r"(en) : "memory");
}

// 3-term bf16 split GEMM accumulate: Ahi*Bhi + Ahi*Blo + Alo*Bhi
__device__ __forceinline__ void issue_mma3(uint32_t dt, uint32_t a_base, uint32_t b_base,
                                           uint32_t sb_unused) {
    uint64_t ah = mk_desc(a_base), al = mk_desc(a_base + 32768);
    uint64_t bh = mk_desc(b_base), bl = mk_desc(b_base + 32768);
    uint32_t en = 0;
    #pragma unroll
    for (int t = 0; t < 3; t++) {
        uint64_t a = (t == 2) ? al : ah;
        uint64_t b = (t == 1) ? bl : bh;
        #pragma unroll
        for (int s = 0; s < 8; s++) {
            uint64_t off = (s < 4) ? (uint64_t)(s * 2) : (uint64_t)(1024 + (s - 4) * 2);
            mma_f16_ss(dt, a + off, b + off, en);
            en = 1;
        }
    }
}
#else
__device__ __forceinline__ float img_read(const unsigned char* smc, int base, int r, int c) {
    uint32_t off = tile_off(r, c);
    unsigned short hi = *(const unsigned short*)(smc + base + off);
    unsigned short lo = *(const unsigned short*)(smc + base + 32768 + off);
    return __bfloat162float(__ushort_as_bfloat16(hi)) + __bfloat162float(__ushort_as_bfloat16(lo));
}
#endif

__global__ void __launch_bounds__(256, 1) k_fgemm(const unsigned char* __restrict__ Aimg,
                                                  const unsigned char* __restrict__ W1img,
                                                  const unsigned char* __restrict__ W2img,
                                                  const float* __restrict__ b1,
                                                  const float* __restrict__ b2,
                                                  float* __restrict__ C) {
    extern __shared__ unsigned char smc[];
    int tid = threadIdx.x;
    int m0 = blockIdx.x * 128;

    // load images + biases
    {
        const float4* as = (const float4*)(Aimg + (size_t)blockIdx.x * 65536);
        float4* ad = (float4*)(smc + SM_A);
        const float4* w1s = (const float4*)W1img;
        float4* w1d = (float4*)(smc + SM_W1);
        const float4* w2s = (const float4*)W2img;
        float4* w2d = (float4*)(smc + SM_W2);
        #pragma unroll
        for (int i = tid; i < 4096; i += 256) { ad[i] = as[i]; w1d[i] = w1s[i]; w2d[i] = w2s[i]; }
        if (tid < 32) {
            ((float4*)(smc + SM_B1))[tid] = ((const float4*)b1)[tid];
            ((float4*)(smc + SM_B2))[tid] = ((const float4*)b2)[tid];
        }
    }

#if HAS_TC
    uint32_t sb = smem_u32(smc);
    int wid = tid >> 5, lid = tid & 31;

    if (wid == 0) TC_ALLOC(sb, 256);
    if (tid == 0) { MBAR_INIT(sb + 16, 1); MBAR_INIT(sb + 32, 1); }
    asm volatile("fence.proxy.async.shared::cta;" ::: "memory");
    __syncthreads();

    uint32_t tmem;
    asm volatile("ld.shared.b32 %0, [%1];" : "=r"(tmem) : "r"(sb));

    if (tid == 0) {
        issue_mma3(tmem, sb + SM_A, sb + SM_W1, 0);
        TC_COMMIT(sb + 16);
    }
    MBAR_WAIT0(sb + 16);
    TC_FENCE_AFTER();

    // epilogue1: warps 0-3 cols 0-63 / 4-7 cols 64-127; r = (wid&3)*32+lid
    int r = (wid & 3) * 32 + lid;
    int cb = (wid >> 2) * 64;
    uint32_t d[64];
    TC_LD_X32(d,      tmem + cb);
    TC_LD_X32(d + 32, tmem + cb + 32);
    TC_WAIT_LD();

    {
        const float* b1s = (const float*)(smc + SM_B1) + cb;
        #pragma unroll
        for (int c = 0; c < 64; c += 8) {
            float v[8];
            #pragma unroll
            for (int q = 0; q < 8; q++)
                v[q] = fmaxf(__uint_as_float(d[c + q]) + b1s[c + q], 0.f);
            unsigned short hh[8], ll[8];
            #pragma unroll
            for (int q = 0; q < 8; q++) split_bf16(v[q], hh[q], ll[q]);
            uint32_t off = tile_off(r, cb + c);
            *(uint4*)(smc + SM_A + off) =
                make_uint4(pack2(hh[0], hh[1]), pack2(hh[2], hh[3]),
                           pack2(hh[4], hh[5]), pack2(hh[6], hh[7]));
            *(uint4*)(smc + SM_A + 32768 + off) =
                make_uint4(pack2(ll[0], ll[1]), pack2(ll[2], ll[3]),
                           pack2(ll[4], ll[5]), pack2(ll[6], ll[7]));
        }
    }
    asm volatile("fence.proxy.async.shared::cta;" ::: "memory");
    __syncthreads();

    if (tid == 0) {
        issue_mma3(tmem + 128, sb + SM_A, sb + SM_W2, 0);
        TC_COMMIT(sb + 32);
    }
    MBAR_WAIT0(sb + 32);
    TC_FENCE_AFTER();

    TC_LD_X32(d,      tmem + 128 + cb);
    TC_LD_X32(d + 32, tmem + 128 + cb + 32);
    TC_WAIT_LD();

    int grow = m0 + r;
    if (grow < NN) {
        const float* b2s = (const float*)(smc + SM_B2) + cb;
        float4* o = (float4*)(C + (size_t)grow * HD + cb);
        #pragma unroll
        for (int c = 0; c < 64; c += 4)
            o[c >> 2] = make_float4(__uint_as_float(d[c])     + b2s[c],
                                    __uint_as_float(d[c + 1]) + b2s[c + 1],
                                    __uint_as_float(d[c + 2]) + b2s[c + 2],
                                    __uint_as_float(d[c + 3]) + b2s[c + 3]);
    }

    __syncthreads();
    if (wid == 0) {
        TC_RELINQ();
        TC_DEALLOC(tmem, 256);
    }
#else
    // ---------- fallback (compiles for plain sm_103; never the fast path) ----------
    __syncthreads();
    int r = tid >> 1, half = tid & 1, cf = half * 64;
    float a[128];
    #pragma unroll 8
    for (int k = 0; k < 128; k++) a[k] = img_read(smc, SM_A, r, k);
    float h1v[64];
    const float* b1s = (const float*)(smc + SM_B1);
    for (int n = 0; n < 64; n++) {
        float s = 0.f;
        #pragma unroll 8
        for (int k = 0; k < 128; k++) s += a[k] * img_read(smc, SM_W1, cf + n, k);
        h1v[n] = fmaxf(s + b1s[cf + n], 0.f);
    }
    __syncthreads();
    float* H = (float*)(smc + SM_A);   // reuse A region as fp32 h1 [128][128]
    for (int n = 0; n < 64; n++) H[r * 128 + cf + n] = h1v[n];
    __syncthreads();
    #pragma unroll 8
    for (int k = 0; k < 128; k++) a[k] = H[r * 128 + k];
    int grow = m0 + r;
    const float* b2s = (const float*)(smc + SM_B2);
    for (int n = 0; n < 64; n++) {
        float s = 0.f;
        #pragma unroll 8
        for (int k = 0; k < 128; k++) s += a[k] * img_read(smc, SM_W2, cf + n, k);
        if (grow < NN) C[(size_t)grow * HD + cf + n] = s + b2s[cf + n];
    }
#endif
}

// ---------------- BN ----------------
__global__ void __launch_bounds__(128) k_colstats(const float* __restrict__ z, int slot) {
    int c = threadIdx.x;
    float s = 0.f, q = 0.f;
    for (int r = blockIdx.x; r < NN; r += gridDim.x) {
        float v = z[(size_t)r * HD + c];
        s += v; q += v * v;
    }
    atomicAdd(&g_sum[slot][c], s);
    atomicAdd(&g_sq[slot][c], q);
}

__global__ void k_bnprep(const float* __restrict__ g,
                         const float* __restrict__ be, int slot) {
    int c = threadIdx.x;
    if (c < HD) {
        float mu  = g_sum[slot][c] * (1.0f / NN);
        float var = g_sq[slot][c] * (1.0f / NN) - mu * mu;
        float sc  = g[c] * rsqrtf(var + 1e-5f);
        g_scale[c] = sc;
        g_shift[c] = be[c] - mu * sc;
    }
}

__global__ void __launch_bounds__(256) k_bnapply(const float* __restrict__ z,
                                                 float* __restrict__ o) {
    int i = blockIdx.x * blockDim.x + threadIdx.x;
    if (i < NN * 32) {
        float4 v = ((const float4*)z)[i];
        int q = i & 31;
        float4 sc = ((const float4*)g_scale)[q];
        float4 sh = ((const float4*)g_shift)[q];
        v.x = fmaxf(fmaf(v.x, sc.x, sh.x), 0.f);
        v.y = fmaxf(fmaf(v.y, sc.y, sh.y), 0.f);
        v.z = fmaxf(fmaf(v.z, sc.z, sh.z), 0.f);
        v.w = fmaxf(fmaf(v.w, sc.w, sh.w), 0.f);
        ((float4*)o)[i] = v;
    }
}

// ---------------- launcher ----------------
extern "C" void kernel_launch(void* const* d_in, const int* in_sizes, int n_in,
                              void* d_out, int out_size) {
    (void)in_sizes; (void)n_in; (void)out_size;
    const float* x    = (const float*)d_in[0];
    const void*  ei   = d_in[1];
    const float* w1_0 = (const float*)d_in[2];
    const float* b1_0 = (const float*)d_in[3];
    const float* w2_0 = (const float*)d_in[4];
    const float* b2_0 = (const float*)d_in[5];
    const float* g_0  = (const float*)d_in[6];
    const float* be_0 = (const float*)d_in[7];
    const float* w1_1 = (const float*)d_in[8];
    const float* b1_1 = (const float*)d_in[9];
    const float* w2_1 = (const float*)d_in[10];
    const float* b2_1 = (const float*)d_in[11];
    const float* g_1  = (const float*)d_in[12];
    const float* be_1 = (const float*)d_in[13];
    float* out = (float*)d_out;

    float* zp;
    unsigned char *ab, *wi;
    cudaGetSymbolAddress((void**)&zp, g_z);
    cudaGetSymbolAddress((void**)&ab, g_abuf);
    cudaGetSymbolAddress((void**)&wi, g_wimg);

    cudaFuncSetAttribute(k_fgemm, cudaFuncAttributeMaxDynamicSharedMemorySize, (int)FG_SMEM);

    // CSR build
    k_detect<<<1, 32>>>((const unsigned int*)ei);
    k_zero<<<(NN + 1 + 255) / 256, 256>>>();
    k_hist<<<(NE + 255) / 256, 256>>>(ei);
    k_blocksum<<<NBLK, SCAN_B>>>();
    k_scanpart<<<1, SCAN_B>>>();
    k_offsets<<<NBLK, SCAN_B>>>();
    k_scatter<<<(NE + 255) / 256, 256>>>(ei);

    // Weight images
    k_wprep<<<64, 256>>>(w1_0, wi + 0 * 65536);
    k_wprep<<<64, 256>>>(w2_0, wi + 1 * 65536);
    k_wprep<<<64, 256>>>(w1_1, wi + 2 * 65536);
    k_wprep<<<64, 256>>>(w2_1, wi + 3 * 65536);

    // Layer 0
    k_aggimg<false><<<(NN + 7) / 8, 256>>>(x, ab);
    k_fgemm<<<GB, 256, FG_SMEM>>>(ab, wi + 0 * 65536, wi + 1 * 65536, b1_0, b2_0, zp);
    k_colstats<<<256, 128>>>(zp, 0);
    k_bnprep<<<1, 128>>>(g_0, be_0, 0);

    // Layer 1 (BN+relu of layer-0 fused into the gather)
    k_aggimg<true><<<(NN + 7) / 8, 256>>>(zp, ab);
    k_fgemm<<<GB, 256, FG_SMEM>>>(ab, wi + 2 * 65536, wi + 3 * 65536, b1_1, b2_1, zp);
    k_colstats<<<256, 128>>>(zp, 1);
    k_bnprep<<<1, 128>>>(g_1, be_1, 1);
    k_bnapply<<<(NN * 32 + 255) / 256, 256>>>(zp, out);
}

// round 14
// speedup vs baseline: 1.1986x; 1.0289x over previous
#include <cuda_runtime.h>
#include <cuda_bf16.h>
#include <cstdint>

#define NN 50000
#define NE 800000
#define HD 128
#define SCAN_B 256
#define NBLK ((NN + SCAN_B - 1) / SCAN_B)   // 196
#define GB   ((NN + 127) / 128)             // 391 gemm tiles

#if defined(__CUDA_ARCH__) && (__CUDA_ARCH__ >= 1000) && \
    (defined(__CUDA_ARCH_FEAT_SM103_ALL) || defined(__CUDA_ARCH_FEAT_SM100_ALL))
#define HAS_TC 1
#else
#define HAS_TC 0
#endif

// ---------------- scratch (__device__ globals: allocation-free) ----------------
__device__ int g_idx64;
__device__ int g_cnt[NN + 1];
__device__ int g_off[NN + 1];
__device__ int g_cur[NN];
__device__ int g_csr[NE];
__device__ int g_part[NBLK];
__device__ int g_partpre[NBLK];
__device__ __align__(16) float g_z[NN * HD];                       // fgemm out (pre-BN)
__device__ __align__(16) unsigned char g_abuf[(size_t)GB * 65536]; // A bf16 hi/lo images
__device__ __align__(16) unsigned char g_wimg[4][65536];           // W bf16 hi/lo images
__device__ float g_sum[2][HD];
__device__ float g_sq[2][HD];
__device__ __align__(16) float g_scale[HD];
__device__ __align__(16) float g_shift[HD];

// ---------------- helpers ----------------
__device__ __forceinline__ uint32_t smem_u32(const void* p) {
    uint32_t a;
    asm("{ .reg .u64 t; cvta.to.shared.u64 t, %1; cvt.u32.u64 %0, t; }" : "=r"(a) : "l"(p));
    return a;
}

// Blocked SW128 atom layout for a 128x128 bf16 tile: atom = 8 rows x 64 cols
// (1024B); atom_offset = (r/8) + (c/64)*16. XOR swizzle at 16B granularity.
__device__ __forceinline__ uint32_t tile_off(int r, int c) {
    uint32_t b = (uint32_t)((((r >> 3) + ((c >> 6) << 4)) << 10) + ((r & 7) << 7) + ((c & 63) << 1));
    return b ^ ((b >> 3) & 0x70);
}

__device__ __forceinline__ void split_bf16(float v, unsigned short& hi, unsigned short& lo) {
    __nv_bfloat16 h = __float2bfloat16_rn(v);
    float res = v - __bfloat162float(h);
    __nv_bfloat16 l = __float2bfloat16_rn(res);
    hi = __bfloat16_as_ushort(h);
    lo = __bfloat16_as_ushort(l);
}

__device__ __forceinline__ uint32_t pack2(unsigned short a, unsigned short b) {
    return (uint32_t)a | ((uint32_t)b << 16);
}

__device__ __forceinline__ int edge_at(const void* ei, long long i) {
    return g_idx64 ? (int)((const long long*)ei)[i] : ((const int*)ei)[i];
}

// ---------------- init: dtype detect + counter zeroing (merged launch) ----------------
__global__ void k_init(const unsigned int* __restrict__ w) {
    int i = blockIdx.x * blockDim.x + threadIdx.x;
    if (i == 0) {
        int is64 = 1;
        for (int q = 1; q < 64; q += 2)
            if (w[q] != 0u) is64 = 0;
        g_idx64 = is64;
    }
    if (i <= NN) g_cnt[i] = 0;
    if (i < HD) {
        g_sum[0][i] = 0.f; g_sq[0][i] = 0.f;
        g_sum[1][i] = 0.f; g_sq[1][i] = 0.f;
    }
}

// ---------------- CSR build ----------------
__global__ void k_hist(const void* __restrict__ ei) {
    int e = blockIdx.x * blockDim.x + threadIdx.x;
    if (e < NE) {
        int d = edge_at(ei, (long long)NE + e);
        atomicAdd(&g_cnt[d], 1);
    }
}

__global__ void k_blocksum() {
    __shared__ int red[SCAN_B];
    int t = threadIdx.x;
    int i = blockIdx.x * SCAN_B + t;
    red[t] = (i < NN) ? g_cnt[i] : 0;
    __syncthreads();
    #pragma unroll
    for (int d = SCAN_B / 2; d > 0; d >>= 1) {
        if (t < d) red[t] += red[t + d];
        __syncthreads();
    }
    if (t == 0) g_part[blockIdx.x] = red[0];
}

__global__ void k_scanpart() {
    __shared__ int s[SCAN_B];
    int t = threadIdx.x;
    int v = (t < NBLK) ? g_part[t] : 0;
    s[t] = v;
    __syncthreads();
    #pragma unroll
    for (int d = 1; d < SCAN_B; d <<= 1) {
        int u = (t >= d) ? s[t - d] : 0;
        __syncthreads();
        s[t] += u;
        __syncthreads();
    }
    if (t < NBLK) g_partpre[t] = s[t] - v;
    if (t == 0) g_off[NN] = NE;
}

__global__ void k_offsets() {
    __shared__ int s[SCAN_B];
    int t = threadIdx.x;
    int i = blockIdx.x * SCAN_B + t;
    int v = (i < NN) ? g_cnt[i] : 0;
    s[t] = v;
    __syncthreads();
    #pragma unroll
    for (int d = 1; d < SCAN_B; d <<= 1) {
        int u = (t >= d) ? s[t - d] : 0;
        __syncthreads();
        s[t] += u;
        __syncthreads();
    }
    if (i < NN) {
        int o = g_partpre[blockIdx.x] + s[t] - v;
        g_off[i] = o;
        g_cur[i] = o;
    }
}

__global__ void k_scatter(const void* __restrict__ ei) {
    int e = blockIdx.x * blockDim.x + threadIdx.x;
    if (e < NE) {
        int d = edge_at(ei, (long long)NE + e);
        int s = edge_at(ei, e);
        int p = atomicAdd(&g_cur[d], 1);
        g_csr[p] = s;
    }
}

// ---------------- aggregation (+optional fused BN+relu) -> bf16 hi/lo image ----------------
template <bool BN>
__global__ void __launch_bounds__(256) k_aggimg(const float* __restrict__ h,
                                                unsigned char* __restrict__ img) {
    int node = blockIdx.x * 8 + (threadIdx.x >> 5);
    if (node >= NN) return;
    int lane = threadIdx.x & 31;

    float4 sc, sh;
    if (BN) {
        sc = ((const float4*)g_scale)[lane];
        sh = ((const float4*)g_shift)[lane];
    }
    const float4* hv = (const float4*)h;

    float4 acc = hv[(size_t)node * 32 + lane];
    if (BN) {
        acc.x = fmaxf(fmaf(acc.x, sc.x, sh.x), 0.f);
        acc.y = fmaxf(fmaf(acc.y, sc.y, sh.y), 0.f);
        acc.z = fmaxf(fmaf(acc.z, sc.z, sh.z), 0.f);
        acc.w = fmaxf(fmaf(acc.w, sc.w, sh.w), 0.f);
    }

    int b = g_off[node], e = g_off[node + 1];
    int j = b;
    for (; j + 4 <= e; j += 4) {
        int s0 = g_csr[j], s1 = g_csr[j + 1], s2 = g_csr[j + 2], s3 = g_csr[j + 3];
        float4 v0 = __ldg(&hv[(size_t)s0 * 32 + lane]);
        float4 v1 = __ldg(&hv[(size_t)s1 * 32 + lane]);
        float4 v2 = __ldg(&hv[(size_t)s2 * 32 + lane]);
        float4 v3 = __ldg(&hv[(size_t)s3 * 32 + lane]);
        if (BN) {
            v0.x = fmaxf(fmaf(v0.x, sc.x, sh.x), 0.f); v0.y = fmaxf(fmaf(v0.y, sc.y, sh.y), 0.f);
            v0.z = fmaxf(fmaf(v0.z, sc.z, sh.z), 0.f); v0.w = fmaxf(fmaf(v0.w, sc.w, sh.w), 0.f);
            v1.x = fmaxf(fmaf(v1.x, sc.x, sh.x), 0.f); v1.y = fmaxf(fmaf(v1.y, sc.y, sh.y), 0.f);
            v1.z = fmaxf(fmaf(v1.z, sc.z, sh.z), 0.f); v1.w = fmaxf(fmaf(v1.w, sc.w, sh.w), 0.f);
            v2.x = fmaxf(fmaf(v2.x, sc.x, sh.x), 0.f); v2.y = fmaxf(fmaf(v2.y, sc.y, sh.y), 0.f);
            v2.z = fmaxf(fmaf(v2.z, sc.z, sh.z), 0.f); v2.w = fmaxf(fmaf(v2.w, sc.w, sh.w), 0.f);
            v3.x = fmaxf(fmaf(v3.x, sc.x, sh.x), 0.f); v3.y = fmaxf(fmaf(v3.y, sc.y, sh.y), 0.f);
            v3.z = fmaxf(fmaf(v3.z, sc.z, sh.z), 0.f); v3.w = fmaxf(fmaf(v3.w, sc.w, sh.w), 0.f);
        }
        acc.x += v0.x + v1.x + v2.x + v3.x;
        acc.y += v0.y + v1.y + v2.y + v3.y;
        acc.z += v0.z + v1.z + v2.z + v3.z;
        acc.w += v0.w + v1.w + v2.w + v3.w;
    }
    for (; j < e; j++) {
        int s = g_csr[j];
        float4 v = __ldg(&hv[(size_t)s * 32 + lane]);
        if (BN) {
            v.x = fmaxf(fmaf(v.x, sc.x, sh.x), 0.f); v.y = fmaxf(fmaf(v.y, sc.y, sh.y), 0.f);
            v.z = fmaxf(fmaf(v.z, sc.z, sh.z), 0.f); v.w = fmaxf(fmaf(v.w, sc.w, sh.w), 0.f);
        }
        acc.x += v.x; acc.y += v.y; acc.z += v.z; acc.w += v.w;
    }

    unsigned short h0, h1, h2, h3, l0, l1, l2, l3;
    split_bf16(acc.x, h0, l0); split_bf16(acc.y, h1, l1);
    split_bf16(acc.z, h2, l2); split_bf16(acc.w, h3, l3);
    int tile = node >> 7, r = node & 127;
    uint32_t off = tile_off(r, lane * 4);
    unsigned char* base = img + (size_t)tile * 65536;
    *(uint2*)(base + off)         = make_uint2(pack2(h0, h1), pack2(h2, h3));
    *(uint2*)(base + 32768 + off) = make_uint2(pack2(l0, l1), pack2(l2, l3));
}

// ---------------- all 4 W -> B-operand images in one launch ----------------
__global__ void k_wprep4(const float* __restrict__ w0, const float* __restrict__ w1,
                         const float* __restrict__ w2, const float* __restrict__ w3) {
    int i = blockIdx.x * blockDim.x + threadIdx.x;
    if (i < 4 * HD * HD) {
        int which = i >> 14, j = i & 16383;
        const float* w = (which == 0) ? w0 : (which == 1) ? w1 : (which == 2) ? w2 : w3;
        int k = j >> 7, n = j & 127;          // w[k][n]
        unsigned short hi, lo;
        split_bf16(w[j], hi, lo);
        uint32_t off = tile_off(n, k);
        unsigned char* img = &g_wimg[which][0];
        *(unsigned short*)(img + off)         = hi;
        *(unsigned short*)(img + 32768 + off) = lo;
    }
}

// ---------------- fused MLP: z = (relu(A@W1+b1))@W2 + b2  (per-tile grid, proven) --------
constexpr int SM_A  = 1024;
constexpr int SM_W1 = SM_A + 65536;       // 66560
constexpr int SM_W2 = SM_W1 + 65536;      // 132096
constexpr int SM_B1 = SM_W2 + 65536;      // 197632
constexpr int SM_B2 = SM_B1 + 512;        // 198144
constexpr size_t FG_SMEM = SM_B2 + 512;   // 198656 (< 227KB cap)

#if HAS_TC
#define TC_ALLOC(sm, n)   asm volatile("tcgen05.alloc.cta_group::1.sync.aligned.shared::cta.b32 [%0], %1;" :: "r"(sm), "r"(n) : "memory")
#define TC_DEALLOC(t, n)  asm volatile("tcgen05.dealloc.cta_group::1.sync.aligned.b32 %0, %1;" :: "r"(t), "r"(n))
#define TC_RELINQ()       asm volatile("tcgen05.relinquish_alloc_permit.cta_group::1.sync.aligned;")
#define TC_COMMIT(mb)     asm volatile("tcgen05.commit.cta_group::1.mbarrier::arrive::one.shared::cluster.b64 [%0];" :: "r"(mb) : "memory")
#define TC_FENCE_AFTER()  asm volatile("tcgen05.fence::after_thread_sync;" ::: "memory")
#define TC_WAIT_LD()      asm volatile("tcgen05.wait::ld.sync.aligned;" ::: "memory")
#define MBAR_INIT(a, c)   asm volatile("mbarrier.init.shared.b64 [%0], %1;" :: "r"(a), "r"(c) : "memory")
#define MBAR_WAIT0(a) do {                                                         \
    asm volatile("{\n\t.reg .pred P1;\n\t"                                         \
        "WL_%=:\n\t"                                                               \
        "mbarrier.try_wait.parity.acquire.cta.shared::cta.b64 P1, [%0], 0, 0x989680;\n\t" \
        "@P1 bra.uni WD_%=;\n\t"                                                   \
        "bra.uni WL_%=;\n\t"                                                       \
        "WD_%=:\n\t}" :: "r"(a) : "memory");                                       \
} while (0)
#define TC_LD_X32(r, ta) \
    asm volatile("tcgen05.ld.sync.aligned.32x32b.x32.b32 " \
        "{%0, %1, %2, %3, %4, %5, %6, %7, %8, %9, %10, %11, %12, %13, %14, %15, " \
        " %16, %17, %18, %19, %20, %21, %22, %23, %24, %25, %26, %27, %28, %29, %30, %31}, [%32];" \
        : "=r"((r)[0]),  "=r"((r)[1]),  "=r"((r)[2]),  "=r"((r)[3]), \
          "=r"((r)[4]),  "=r"((r)[5]),  "=r"((r)[6]),  "=r"((r)[7]), \
          "=r"((r)[8]),  "=r"((r)[9]),  "=r"((r)[10]), "=r"((r)[11]), \
          "=r"((r)[12]), "=r"((r)[13]), "=r"((r)[14]), "=r"((r)[15]), \
          "=r"((r)[16]), "=r"((r)[17]), "=r"((r)[18]), "=r"((r)[19]), \
          "=r"((r)[20]), "=r"((r)[21]), "=r"((r)[22]), "=r"((r)[23]), \
          "=r"((r)[24]), "=r"((r)[25]), "=r"((r)[26]), "=r"((r)[27]), \
          "=r"((r)[28]), "=r"((r)[29]), "=r"((r)[30]), "=r"((r)[31]) \
        : "r"(ta))

static constexpr uint64_t DESC_BASE =
    (uint64_t(2) << 61) | (uint64_t(1) << 46) | (uint64_t(64) << 32) | (uint64_t(1) << 16);
__device__ __forceinline__ uint64_t mk_desc(uint32_t addr) {
    return DESC_BASE | ((uint64_t)(addr >> 4) & 0x3FFF);
}
// idesc kind::f16: dtype F32, a/b BF16 K-major, M=128, N=128
#define IDESC_F16 ((8u << 24) | (16u << 17) | (1u << 10) | (1u << 7) | (1u << 4))

__device__ __forceinline__ void mma_f16_ss(uint32_t d, uint64_t ad, uint64_t bd, uint32_t en) {
    asm volatile(
        "{\n\t.reg .pred p;\n\tsetp.ne.u32 p, %5, 0;\n\t"
        "tcgen05.mma.cta_group::1.kind::f16 [%0], %1, %2, %3, {%4, %4, %4, %4}, p;\n\t}"
        :: "r"(d), "l"(ad), "l"(bd), "r"(IDESC_F16), "r"(0u), "r"(en) : "memory");
}

// 3-term bf16 split GEMM accumulate: Ahi*Bhi + Ahi*Blo + Alo*Bhi
__device__ __forceinline__ void issue_mma3(uint32_t dt, uint32_t a_base, uint32_t b_base) {
    uint64_t ah = mk_desc(a_base), al = mk_desc(a_base + 32768);
    uint64_t bh = mk_desc(b_base), bl = mk_desc(b_base + 32768);
    uint32_t en = 0;
    #pragma unroll
    for (int t = 0; t < 3; t++) {
        uint64_t a = (t == 2) ? al : ah;
        uint64_t b = (t == 1) ? bl : bh;
        #pragma unroll
        for (int s = 0; s < 8; s++) {
            uint64_t off = (s < 4) ? (uint64_t)(s * 2) : (uint64_t)(1024 + (s - 4) * 2);
            mma_f16_ss(dt, a + off, b + off, en);
            en = 1;
        }
    }
}
#else
__device__ __forceinline__ float img_read(const unsigned char* smc, int base, int r, int c) {
    uint32_t off = tile_off(r, c);
    unsigned short hi = *(const unsigned short*)(smc + base + off);
    unsigned short lo = *(const unsigned short*)(smc + base + 32768 + off);
    return __bfloat162float(__ushort_as_bfloat16(hi)) + __bfloat162float(__ushort_as_bfloat16(lo));
}
#endif

__global__ void __launch_bounds__(256, 1) k_fgemm(const unsigned char* __restrict__ Aimg,
                                                  const unsigned char* __restrict__ W1img,
                                                  const unsigned char* __restrict__ W2img,
                                                  const float* __restrict__ b1,
                                                  const float* __restrict__ b2,
                                                  float* __restrict__ C) {
    extern __shared__ unsigned char smc[];
    int tid = threadIdx.x;
    int m0 = blockIdx.x * 128;

    // load images + biases
    {
        const float4* as = (const float4*)(Aimg + (size_t)blockIdx.x * 65536);
        float4* ad = (float4*)(smc + SM_A);
        const float4* w1s = (const float4*)W1img;
        float4* w1d = (float4*)(smc + SM_W1);
        const float4* w2s = (const float4*)W2img;
        float4* w2d = (float4*)(smc + SM_W2);
        #pragma unroll
        for (int i = tid; i < 4096; i += 256) { ad[i] = as[i]; w1d[i] = w1s[i]; w2d[i] = w2s[i]; }
        if (tid < 32) {
            ((float4*)(smc + SM_B1))[tid] = ((const float4*)b1)[tid];
            ((float4*)(smc + SM_B2))[tid] = ((const float4*)b2)[tid];
        }
    }

#if HAS_TC
    uint32_t sb = smem_u32(smc);
    int wid = tid >> 5, lid = tid & 31;

    if (wid == 0) TC_ALLOC(sb, 256);
    if (tid == 0) { MBAR_INIT(sb + 16, 1); MBAR_INIT(sb + 32, 1); }
    asm volatile("fence.proxy.async.shared::cta;" ::: "memory");
    __syncthreads();

    uint32_t tmem;
    asm volatile("ld.shared.b32 %0, [%1];" : "=r"(tmem) : "r"(sb));

    if (tid == 0) {
        issue_mma3(tmem, sb + SM_A, sb + SM_W1);
        TC_COMMIT(sb + 16);
    }
    MBAR_WAIT0(sb + 16);
    TC_FENCE_AFTER();

    // epilogue1: warps 0-3 cols 0-63 / 4-7 cols 64-127; r = (wid&3)*32+lid
    int r = (wid & 3) * 32 + lid;
    int cb = (wid >> 2) * 64;
    uint32_t d[64];
    TC_LD_X32(d,      tmem + cb);
    TC_LD_X32(d + 32, tmem + cb + 32);
    TC_WAIT_LD();

    {
        const float* b1s = (const float*)(smc + SM_B1) + cb;
        #pragma unroll
        for (int c = 0; c < 64; c += 8) {
            float v[8];
            #pragma unroll
            for (int q = 0; q < 8; q++)
                v[q] = fmaxf(__uint_as_float(d[c + q]) + b1s[c + q], 0.f);
            unsigned short hh[8], ll[8];
            #pragma unroll
            for (int q = 0; q < 8; q++) split_bf16(v[q], hh[q], ll[q]);
            uint32_t off = tile_off(r, cb + c);
            *(uint4*)(smc + SM_A + off) =
                make_uint4(pack2(hh[0], hh[1]), pack2(hh[2], hh[3]),
                           pack2(hh[4], hh[5]), pack2(hh[6], hh[7]));
            *(uint4*)(smc + SM_A + 32768 + off) =
                make_uint4(pack2(ll[0], ll[1]), pack2(ll[2], ll[3]),
                           pack2(ll[4], ll[5]), pack2(ll[6], ll[7]));
        }
    }
    asm volatile("fence.proxy.async.shared::cta;" ::: "memory");
    __syncthreads();

    if (tid == 0) {
        issue_mma3(tmem + 128, sb + SM_A, sb + SM_W2);
        TC_COMMIT(sb + 32);
    }
    MBAR_WAIT0(sb + 32);
    TC_FENCE_AFTER();

    TC_LD_X32(d,      tmem + 128 + cb);
    TC_LD_X32(d + 32, tmem + 128 + cb + 32);
    TC_WAIT_LD();

    int grow = m0 + r;
    if (grow < NN) {
        const float* b2s = (const float*)(smc + SM_B2) + cb;
        float4* o = (float4*)(C + (size_t)grow * HD + cb);
        #pragma unroll
        for (int c = 0; c < 64; c += 4)
            o[c >> 2] = make_float4(__uint_as_float(d[c])     + b2s[c],
                                    __uint_as_float(d[c + 1]) + b2s[c + 1],
                                    __uint_as_float(d[c + 2]) + b2s[c + 2],
                                    __uint_as_float(d[c + 3]) + b2s[c + 3]);
    }

    __syncthreads();
    if (wid == 0) {
        TC_RELINQ();
        TC_DEALLOC(tmem, 256);
    }
#else
    // ---------- fallback (compiles for plain sm_103; never the fast path) ----------
    __syncthreads();
    int r = tid >> 1, half = tid & 1, cf = half * 64;
    float a[128];
    #pragma unroll 8
    for (int k = 0; k < 128; k++) a[k] = img_read(smc, SM_A, r, k);
    float h1v[64];
    const float* b1s = (const float*)(smc + SM_B1);
    for (int n = 0; n < 64; n++) {
        float s = 0.f;
        #pragma unroll 8
        for (int k = 0; k < 128; k++) s += a[k] * img_read(smc, SM_W1, cf + n, k);
        h1v[n] = fmaxf(s + b1s[cf + n], 0.f);
    }
    __syncthreads();
    float* H = (float*)(smc + SM_A);   // reuse A region as fp32 h1 [128][128]
    for (int n = 0; n < 64; n++) H[r * 128 + cf + n] = h1v[n];
    __syncthreads();
    #pragma unroll 8
    for (int k = 0; k < 128; k++) a[k] = H[r * 128 + k];
    int grow = m0 + r;
    const float* b2s = (const float*)(smc + SM_B2);
    for (int n = 0; n < 64; n++) {
        float s = 0.f;
        #pragma unroll 8
        for (int k = 0; k < 128; k++) s += a[k] * img_read(smc, SM_W2, cf + n, k);
        if (grow < NN) C[(size_t)grow * HD + cf + n] = s + b2s[cf + n];
    }
#endif
}

// ---------------- BN ----------------
__global__ void __launch_bounds__(128) k_colstats(const float* __restrict__ z, int slot) {
    int c = threadIdx.x;
    float s = 0.f, q = 0.f;
    for (int r = blockIdx.x; r < NN; r += gridDim.x) {
        float v = z[(size_t)r * HD + c];
        s += v; q += v * v;
    }
    atomicAdd(&g_sum[slot][c], s);
    atomicAdd(&g_sq[slot][c], q);
}

__global__ void k_bnprep(const float* __restrict__ g,
                         const float* __restrict__ be, int slot) {
    int c = threadIdx.x;
    if (c < HD) {
        float mu  = g_sum[slot][c] * (1.0f / NN);
        float var = g_sq[slot][c] * (1.0f / NN) - mu * mu;
        float sc  = g[c] * rsqrtf(var + 1e-5f);
        g_scale[c] = sc;
        g_shift[c] = be[c] - mu * sc;
    }
}

__global__ void __launch_bounds__(256) k_bnapply(const float* __restrict__ z,
                                                 float* __restrict__ o) {
    int i = blockIdx.x * blockDim.x + threadIdx.x;
    if (i < NN * 32) {
        float4 v = ((const float4*)z)[i];
        int q = i & 31;
        float4 sc = ((const float4*)g_scale)[q];
        float4 sh = ((const float4*)g_shift)[q];
        v.x = fmaxf(fmaf(v.x, sc.x, sh.x), 0.f);
        v.y = fmaxf(fmaf(v.y, sc.y, sh.y), 0.f);
        v.z = fmaxf(fmaf(v.z, sc.z, sh.z), 0.f);
        v.w = fmaxf(fmaf(v.w, sc.w, sh.w), 0.f);
        ((float4*)o)[i] = v;
    }
}

// ---------------- launcher ----------------
extern "C" void kernel_launch(void* const* d_in, const int* in_sizes, int n_in,
                              void* d_out, int out_size) {
    (void)in_sizes; (void)n_in; (void)out_size;
    const float* x    = (const float*)d_in[0];
    const void*  ei   = d_in[1];
    const float* w1_0 = (const float*)d_in[2];
    const float* b1_0 = (const float*)d_in[3];
    const float* w2_0 = (const float*)d_in[4];
    const float* b2_0 = (const float*)d_in[5];
    const float* g_0  = (const float*)d_in[6];
    const float* be_0 = (const float*)d_in[7];
    const float* w1_1 = (const float*)d_in[8];
    const float* b1_1 = (const float*)d_in[9];
    const float* w2_1 = (const float*)d_in[10];
    const float* b2_1 = (const float*)d_in[11];
    const float* g_1  = (const float*)d_in[12];
    const float* be_1 = (const float*)d_in[13];
    float* out = (float*)d_out;

    float* zp;
    unsigned char *ab, *wi;
    cudaGetSymbolAddress((void**)&zp, g_z);
    cudaGetSymbolAddress((void**)&ab, g_abuf);
    cudaGetSymbolAddress((void**)&wi, g_wimg);

    cudaFuncSetAttribute(k_fgemm, cudaFuncAttributeMaxDynamicSharedMemorySize, (int)FG_SMEM);

    // CSR build + init
    k_init<<<(NN + 1 + 255) / 256, 256>>>((const unsigned int*)ei);
    k_hist<<<(NE + 255) / 256, 256>>>(ei);
    k_blocksum<<<NBLK, SCAN_B>>>();
    k_scanpart<<<1, SCAN_B>>>();
    k_offsets<<<NBLK, SCAN_B>>>();
    k_scatter<<<(NE + 255) / 256, 256>>>(ei);

    // Weight images (one launch)
    k_wprep4<<<(4 * HD * HD + 255) / 256, 256>>>(w1_0, w2_0, w1_1, w2_1);

    // Layer 0
    k_aggimg<false><<<(NN + 7) / 8, 256>>>(x, ab);
    k_fgemm<<<GB, 256, FG_SMEM>>>(ab, wi + 0 * 65536, wi + 1 * 65536, b1_0, b2_0, zp);
    k_colstats<<<256, 128>>>(zp, 0);
    k_bnprep<<<1, 128>>>(g_0, be_0, 0);

    // Layer 1 (BN+relu of layer 0 fused into the gather)
    k_aggimg<true><<<(NN + 7) / 8, 256>>>(zp, ab);
    k_fgemm<<<GB, 256, FG_SMEM>>>(ab, wi + 2 * 65536, wi + 3 * 65536, b1_1, b2_1, zp);
    k_colstats<<<256, 128>>>(zp, 1);
    k_bnprep<<<1, 128>>>(g_1, be_1, 1);
    k_bnapply<<<(NN * 32 + 255) / 256, 256>>>(zp, out);
}